// round 2
// baseline (speedup 1.0000x reference)
#include <cuda_runtime.h>
#include <cuda_bf16.h>

#define NWIN 64
#define NTOK 49
#define CDIM 128
#define NH   4
#define HD   32
#define HDP  33   // padded head-dim stride -> conflict-free LDS
#define NREL 169
#define ROWS_PAD 52   // 4 row-groups x 13

typedef unsigned long long u64;

// smem layout (floats):
//   xsd  : 52*128*2    = 13312  (duplicated (v,v) activation buffer; input, then attn out)
//   qs   : 4*49*33     = 6468
//   ks   : 4*49*33     = 6468
//   vs   : 4*49*33     = 6468
//   ms   : 49*49       = 2401
//   bt   : 169*4       = 676
// total = 35793 floats = 143,172 bytes
#define SMEM_FLOATS 35793

__device__ __forceinline__ u64 fma2(u64 a, u64 b, u64 c) {
    u64 d;
    asm("fma.rn.f32x2 %0, %1, %2, %3;" : "=l"(d) : "l"(a), "l"(b), "l"(c));
    return d;
}
__device__ __forceinline__ u64 mul2(u64 a, u64 b) {
    u64 d;
    asm("mul.rn.f32x2 %0, %1, %2;" : "=l"(d) : "l"(a), "l"(b));
    return d;
}
__device__ __forceinline__ float2 unpk(u64 a) {
    union { u64 u; float2 f; } cv; cv.u = a; return cv.f;
}

__global__ __launch_bounds__(256, 1)
void swin_window_attn_kernel(const float* __restrict__ x,
                             const float* __restrict__ mask,
                             const float* __restrict__ qkv_w,
                             const float* __restrict__ qkv_b,
                             const float* __restrict__ proj_w,
                             const float* __restrict__ proj_b,
                             const float* __restrict__ bias_table,
                             float* __restrict__ out)
{
    extern __shared__ float smem[];
    float* xsd = smem;                         // 52*128*2 (pairs)
    float* qs  = xsd + ROWS_PAD * CDIM * 2;
    float* ks  = qs + NH * NTOK * HDP;
    float* vs  = ks + NH * NTOK * HDP;
    float* ms  = vs + NH * NTOK * HDP;
    float* bt  = ms + NTOK * NTOK;

    const int b   = blockIdx.x;
    const int tid = threadIdx.x;
    const int txp = tid & 63;                  // output column-pair (cols 2*txp, 2*txp+1)
    const int typ = tid >> 6;                  // row group 0..3, 13 rows each
    const int row0 = typ * 13;

    // ---- Phase 0: stage inputs (x duplicated into pairs) ----
    {
        const float* xb = x + (size_t)b * NTOK * CDIM;
        float2* xp = (float2*)xsd;
        for (int i = tid; i < NTOK * CDIM; i += 256) {
            const float v = xb[i];
            xp[i] = make_float2(v, v);
        }
        const float* mb = mask + (size_t)(b & (NWIN - 1)) * NTOK * NTOK;
        for (int i = tid; i < NTOK * NTOK; i += 256) ms[i] = mb[i];
        for (int i = tid; i < NREL * NH; i += 256) bt[i] = bias_table[i];
    }
    __syncthreads();

    // ---- Phase 1: QKV GEMM [49x128] @ [128x384], packed f32x2 ----
    {
        u64 acc0[13], acc1[13], acc2[13];
        const u64 b0 = *(const u64*)(qkv_b + 2 * txp);
        const u64 b1 = *(const u64*)(qkv_b + 128 + 2 * txp);
        const u64 b2 = *(const u64*)(qkv_b + 256 + 2 * txp);
        #pragma unroll
        for (int r = 0; r < 13; r++) { acc0[r] = b0; acc1[r] = b1; acc2[r] = b2; }

        const float* wp = qkv_w + 2 * txp;
        const u64* xr = (const u64*)xsd + row0 * CDIM;

        #pragma unroll 2
        for (int k = 0; k < CDIM; k++) {
            const u64 w0 = *(const u64*)(wp + k * 384);
            const u64 w1 = *(const u64*)(wp + k * 384 + 128);
            const u64 w2 = *(const u64*)(wp + k * 384 + 256);
            #pragma unroll
            for (int r = 0; r < 13; r++) {
                const u64 xx = xr[r * CDIM + k];   // LDS.64 broadcast (v,v)
                acc0[r] = fma2(xx, w0, acc0[r]);
                acc1[r] = fma2(xx, w1, acc1[r]);
                acc2[r] = fma2(xx, w2, acc2[r]);
            }
        }

        // cols (2*txp, 2*txp+1) are always within the same head (even base)
        const int c  = 2 * txp;
        const int h0 = c >> 5;
        const int d0 = c & 31;
        const unsigned sbits = __float_as_uint(0.17677669529663687f);  // 32^-0.5
        const u64 spair = ((u64)sbits << 32) | sbits;

        #pragma unroll
        for (int r = 0; r < 13; r++) {
            const int row = row0 + r;
            if (row < NTOK) {
                const int o = (h0 * NTOK + row) * HDP + d0;
                const float2 q2 = unpk(mul2(acc0[r], spair));
                const float2 k2 = unpk(acc1[r]);
                const float2 v2 = unpk(acc2[r]);
                qs[o] = q2.x; qs[o + 1] = q2.y;
                ks[o] = k2.x; ks[o + 1] = k2.y;
                vs[o] = v2.x; vs[o + 1] = v2.y;
            }
        }
    }
    __syncthreads();

    // ---- Phase 2: attention (2 warps per head), probs kept in registers ----
    {
        const int warp = tid >> 5;
        const int lane = tid & 31;
        const int h    = warp >> 1;
        const int sub  = warp & 1;

        for (int i = sub; i < NTOK; i += 2) {
            const float* qrow = qs + (h * NTOK + i) * HDP;
            const int j0 = lane;
            const int j1 = lane + 32;
            const float* kr0 = ks + (h * NTOK + j0) * HDP;
            const float* kr1 = ks + (h * NTOK + (j1 < NTOK ? j1 : 0)) * HDP;
            float a0 = 0.f, a1 = 0.f;
            #pragma unroll
            for (int d = 0; d < HD; d++) {
                const float qv = qrow[d];                  // broadcast
                a0 += qv * kr0[d];                         // conflict-free (pad 33)
                a1 += qv * kr1[d];
            }
            const int yi = i / 7, xi = i % 7;
            {
                const int yj = j0 / 7, xj = j0 % 7;
                const int idx = (yi - yj + 6) * 13 + (xi - xj + 6);
                a0 += bt[idx * NH + h] + ms[i * NTOK + j0];
            }
            if (j1 < NTOK) {
                const int yj = j1 / 7, xj = j1 % 7;
                const int idx = (yi - yj + 6) * 13 + (xi - xj + 6);
                a1 += bt[idx * NH + h] + ms[i * NTOK + j1];
            } else {
                a1 = -1e30f;
            }
            // softmax across the warp (49 live values)
            float mx = fmaxf(a0, a1);
            #pragma unroll
            for (int o = 16; o > 0; o >>= 1)
                mx = fmaxf(mx, __shfl_xor_sync(0xffffffffu, mx, o));
            const float e0 = __expf(a0 - mx);
            const float e1 = (j1 < NTOK) ? __expf(a1 - mx) : 0.f;
            float sm = e0 + e1;
            #pragma unroll
            for (int o = 16; o > 0; o >>= 1)
                sm += __shfl_xor_sync(0xffffffffu, sm, o);
            const float inv = 1.f / sm;
            const float p0 = e0 * inv;
            const float p1 = e1 * inv;

            // P @ V via shuffle broadcast; lane = head-dim
            float acc = 0.f;
            #pragma unroll
            for (int j = 0; j < 32; j++)
                acc += __shfl_sync(0xffffffffu, p0, j) * vs[(h * NTOK + j) * HDP + lane];
            #pragma unroll
            for (int j = 0; j < 17; j++)
                acc += __shfl_sync(0xffffffffu, p1, j) * vs[(h * NTOK + 32 + j) * HDP + lane];

            // write duplicated pair for phase-3 broadcast reads
            ((float2*)xsd)[i * CDIM + h * HD + lane] = make_float2(acc, acc);
        }
    }
    __syncthreads();

    // ---- Phase 3: proj GEMM [49x128] @ [128x128] + bias, packed f32x2 ----
    {
        u64 acc[13];
        const u64 pb = *(const u64*)(proj_b + 2 * txp);
        #pragma unroll
        for (int r = 0; r < 13; r++) acc[r] = pb;

        const float* wp = proj_w + 2 * txp;
        const u64* xr = (const u64*)xsd + row0 * CDIM;

        #pragma unroll 2
        for (int k = 0; k < CDIM; k++) {
            const u64 w = *(const u64*)(wp + k * CDIM);
            #pragma unroll
            for (int r = 0; r < 13; r++)
                acc[r] = fma2(xr[r * CDIM + k], w, acc[r]);
        }

        float* ob = out + (size_t)b * NTOK * CDIM;
        #pragma unroll
        for (int r = 0; r < 13; r++) {
            const int row = row0 + r;
            if (row < NTOK)
                *(float2*)(ob + row * CDIM + 2 * txp) = unpk(acc[r]);
        }
    }
}

extern "C" void kernel_launch(void* const* d_in, const int* in_sizes, int n_in,
                              void* d_out, int out_size)
{
    const float* x      = (const float*)d_in[0];
    const float* mask   = (const float*)d_in[1];
    const float* qkv_w  = (const float*)d_in[2];
    const float* qkv_b  = (const float*)d_in[3];
    const float* proj_w = (const float*)d_in[4];
    const float* proj_b = (const float*)d_in[5];
    const float* btab   = (const float*)d_in[6];

    const int n_windows = in_sizes[0] / (NTOK * CDIM);   // 4096
    const size_t smem_bytes = SMEM_FLOATS * sizeof(float);

    cudaFuncSetAttribute(swin_window_attn_kernel,
                         cudaFuncAttributeMaxDynamicSharedMemorySize,
                         (int)smem_bytes);

    swin_window_attn_kernel<<<n_windows, 256, smem_bytes>>>(
        x, mask, qkv_w, qkv_b, proj_w, proj_b, btab, (float*)d_out);
}

// round 3
// speedup vs baseline: 1.6701x; 1.6701x over previous
#include <cuda_runtime.h>
#include <cuda_bf16.h>

#define NWIN 64
#define NTOK 49
#define CDIM 128
#define NH   4
#define HD   32
#define NREL 169
#define KSTR 52          // k-major row stride (rows 0..51), 208B = 16B-aligned per k

typedef unsigned long long u64;

// smem layout (floats):
//   xs : 128*52 = 6656   (k-major activations; reused as k-major attention output)
//   qs : 4*49*32 = 6272  ([h][tok][d])
//   kt : 4*32*49 = 6272  ([h][d][tok]  — transposed for conflict-free QK^T)
//   vs : 4*49*32 = 6272  ([h][tok][d])
//   ms : 49*49   = 2401
//   bt : 169*4   = 676
// total = 28,549 floats = 114,196 bytes  ->  2 CTAs/SM (228.4KB of 233KB)
#define SMEM_FLOATS 28549

__device__ __forceinline__ u64 fma2(u64 a, u64 b, u64 c) {
    u64 d;
    asm("fma.rn.f32x2 %0, %1, %2, %3;" : "=l"(d) : "l"(a), "l"(b), "l"(c));
    return d;
}
__device__ __forceinline__ u64 mul2(u64 a, u64 b) {
    u64 d;
    asm("mul.rn.f32x2 %0, %1, %2;" : "=l"(d) : "l"(a), "l"(b));
    return d;
}
__device__ __forceinline__ u64 dup(float v) {
    u64 d;
    asm("mov.b64 %0, {%1, %1};" : "=l"(d) : "f"(v));
    return d;
}
__device__ __forceinline__ float2 unpk(u64 a) {
    union { u64 u; float2 f; } cv; cv.u = a; return cv.f;
}

__global__ __launch_bounds__(256, 2)
void swin_window_attn_kernel(const float* __restrict__ x,
                             const float* __restrict__ mask,
                             const float* __restrict__ qkv_w,
                             const float* __restrict__ qkv_b,
                             const float* __restrict__ proj_w,
                             const float* __restrict__ proj_b,
                             const float* __restrict__ bias_table,
                             float* __restrict__ out)
{
    extern __shared__ float smem[];
    float* xs = smem;                      // 128*52, k-major
    float* qs = xs + CDIM * KSTR;          // [h][tok][32]
    float* kt = qs + NH * NTOK * HD;       // [h][32][tok]
    float* vs = kt + NH * HD * NTOK;       // [h][tok][32]
    float* ms = vs + NH * NTOK * HD;
    float* bt = ms + NTOK * NTOK;

    const int b   = blockIdx.x;
    const int tid = threadIdx.x;
    const int c   = tid & 127;             // output column 0..127 (per chunk)
    const int grp = tid >> 7;              // row-pair group: 0 -> rows 0..25, 1 -> rows 24..49
    const int rbase = grp * 24;            // 16B-aligned smem row offset (24*4 = 96B)

    // ---- Phase 0: stage inputs (x transposed to k-major) ----
    {
        const float* xb = x + (size_t)b * NTOK * CDIM;
        for (int i = tid; i < NTOK * CDIM; i += 256) {
            const int t  = i >> 7;
            const int ch = i & 127;
            xs[ch * KSTR + t] = xb[i];
        }
        // zero the pad rows 49..51 so group-B hi lanes stay finite
        for (int i = tid; i < CDIM * 3; i += 256) {
            const int ch = i / 3, r = 49 + (i % 3);
            xs[ch * KSTR + r] = 0.f;
        }
        const float* mb = mask + (size_t)(b & (NWIN - 1)) * NTOK * NTOK;
        for (int i = tid; i < NTOK * NTOK; i += 256) ms[i] = mb[i];
        for (int i = tid; i < NREL * NH; i += 256) bt[i] = bias_table[i];
    }
    __syncthreads();

    // ---- Phase 1: QKV GEMM [49x128]@[128x384], row-pair f32x2 ----
    {
        u64 acc0[13], acc1[13], acc2[13];
        const u64 b0 = dup(qkv_b[c]);
        const u64 b1 = dup(qkv_b[128 + c]);
        const u64 b2 = dup(qkv_b[256 + c]);
        #pragma unroll
        for (int p = 0; p < 13; p++) { acc0[p] = b0; acc1[p] = b1; acc2[p] = b2; }

        const float* wq = qkv_w + c;

        #pragma unroll 2
        for (int k = 0; k < CDIM; k++) {
            u64 xr[13];
            {
                const float4* src = (const float4*)(xs + k * KSTR + rbase);
                float4* dst = (float4*)xr;
                #pragma unroll
                for (int i = 0; i < 6; i++) dst[i] = src[i];         // LDS.128 broadcast
                ((float2*)xr)[12] = ((const float2*)(xs + k * KSTR + rbase))[12];
            }
            const u64 w0 = dup(wq[k * 384]);
            const u64 w1 = dup(wq[k * 384 + 128]);
            const u64 w2 = dup(wq[k * 384 + 256]);
            #pragma unroll
            for (int p = 0; p < 13; p++) {
                acc0[p] = fma2(xr[p], w0, acc0[p]);
                acc1[p] = fma2(xr[p], w1, acc1[p]);
                acc2[p] = fma2(xr[p], w2, acc2[p]);
            }
        }

        const int h0 = c >> 5;
        const int d0 = c & 31;
        const u64 spair = dup(0.17677669529663687f);   // 32^-0.5

        #pragma unroll
        for (int p = 0; p < 13; p++) {
            const int r0 = rbase + 2 * p;
            const int r1 = r0 + 1;
            const float2 q2 = unpk(mul2(acc0[p], spair));
            const float2 k2 = unpk(acc1[p]);
            const float2 v2 = unpk(acc2[p]);
            // rows 24/25 written by both groups with identical values (benign)
            if (r0 < NTOK) {
                qs[(h0 * NTOK + r0) * HD + d0] = q2.x;
                kt[(h0 * HD + d0) * NTOK + r0] = k2.x;
                vs[(h0 * NTOK + r0) * HD + d0] = v2.x;
            }
            if (r1 < NTOK) {
                qs[(h0 * NTOK + r1) * HD + d0] = q2.y;
                kt[(h0 * HD + d0) * NTOK + r1] = k2.y;
                vs[(h0 * NTOK + r1) * HD + d0] = v2.y;
            }
        }
    }
    __syncthreads();

    // ---- Phase 2: attention (2 warps/head), probs in registers ----
    {
        const int warp = tid >> 5;
        const int lane = tid & 31;
        const int h    = warp >> 1;
        const int sub  = warp & 1;

        for (int i = sub; i < NTOK; i += 2) {
            const float* qrow = qs + (h * NTOK + i) * HD;
            const float* kth  = kt + h * HD * NTOK;
            const int j0 = lane;
            const int j1 = lane + 32;
            float a0 = 0.f, a1 = 0.f;
            #pragma unroll
            for (int d = 0; d < HD; d++) {
                const float qv = qrow[d];                 // broadcast
                const float* krow = kth + d * NTOK;
                a0 += qv * krow[j0];                      // consecutive -> conflict-free
                a1 += qv * ((j1 < NTOK) ? krow[j1] : 0.f);
            }
            const int yi = i / 7, xi = i % 7;
            {
                const int yj = j0 / 7, xj = j0 % 7;
                const int idx = (yi - yj + 6) * 13 + (xi - xj + 6);
                a0 += bt[idx * NH + h] + ms[i * NTOK + j0];
            }
            if (j1 < NTOK) {
                const int yj = j1 / 7, xj = j1 % 7;
                const int idx = (yi - yj + 6) * 13 + (xi - xj + 6);
                a1 += bt[idx * NH + h] + ms[i * NTOK + j1];
            } else {
                a1 = -1e30f;
            }
            float mx = fmaxf(a0, a1);
            #pragma unroll
            for (int o = 16; o > 0; o >>= 1)
                mx = fmaxf(mx, __shfl_xor_sync(0xffffffffu, mx, o));
            const float e0 = __expf(a0 - mx);
            const float e1 = (j1 < NTOK) ? __expf(a1 - mx) : 0.f;
            float sm = e0 + e1;
            #pragma unroll
            for (int o = 16; o > 0; o >>= 1)
                sm += __shfl_xor_sync(0xffffffffu, sm, o);
            const float inv = 1.f / sm;
            const float p0 = e0 * inv;
            const float p1 = e1 * inv;

            // P @ V via shuffle broadcast; lane = head-dim
            float acc = 0.f;
            #pragma unroll
            for (int j = 0; j < 32; j++)
                acc += __shfl_sync(0xffffffffu, p0, j) * vs[(h * NTOK + j) * HD + lane];
            #pragma unroll
            for (int j = 0; j < 17; j++)
                acc += __shfl_sync(0xffffffffu, p1, j) * vs[(h * NTOK + 32 + j) * HD + lane];

            // k-major write for phase 3 (channel = h*32+lane)
            xs[(h * HD + lane) * KSTR + i] = acc;
        }
    }
    __syncthreads();

    // ---- Phase 3: proj GEMM [49x128]@[128x128] + bias, row-pair f32x2 ----
    {
        u64 acc[13];
        const u64 pb = dup(proj_b[c]);
        #pragma unroll
        for (int p = 0; p < 13; p++) acc[p] = pb;

        const float* wp = proj_w + c;

        #pragma unroll 2
        for (int k = 0; k < CDIM; k++) {
            u64 xr[13];
            {
                const float4* src = (const float4*)(xs + k * KSTR + rbase);
                float4* dst = (float4*)xr;
                #pragma unroll
                for (int i = 0; i < 6; i++) dst[i] = src[i];
                ((float2*)xr)[12] = ((const float2*)(xs + k * KSTR + rbase))[12];
            }
            const u64 w = dup(wp[k * CDIM]);
            #pragma unroll
            for (int p = 0; p < 13; p++)
                acc[p] = fma2(xr[p], w, acc[p]);
        }

        float* ob = out + (size_t)b * NTOK * CDIM;
        #pragma unroll
        for (int p = 0; p < 13; p++) {
            const int r0 = rbase + 2 * p;
            const int r1 = r0 + 1;
            const float2 v2 = unpk(acc[p]);
            if (r0 < NTOK) ob[r0 * CDIM + c] = v2.x;
            if (r1 < NTOK) ob[r1 * CDIM + c] = v2.y;
        }
    }
}

extern "C" void kernel_launch(void* const* d_in, const int* in_sizes, int n_in,
                              void* d_out, int out_size)
{
    const float* x      = (const float*)d_in[0];
    const float* mask   = (const float*)d_in[1];
    const float* qkv_w  = (const float*)d_in[2];
    const float* qkv_b  = (const float*)d_in[3];
    const float* proj_w = (const float*)d_in[4];
    const float* proj_b = (const float*)d_in[5];
    const float* btab   = (const float*)d_in[6];

    const int n_windows = in_sizes[0] / (NTOK * CDIM);   // 4096
    const size_t smem_bytes = SMEM_FLOATS * sizeof(float);

    cudaFuncSetAttribute(swin_window_attn_kernel,
                         cudaFuncAttributeMaxDynamicSharedMemorySize,
                         (int)smem_bytes);

    swin_window_attn_kernel<<<n_windows, 256, smem_bytes>>>(
        x, mask, qkv_w, qkv_b, proj_w, proj_b, btab, (float*)d_out);
}